// round 2
// baseline (speedup 1.0000x reference)
#include <cuda_runtime.h>
#include <cstdint>

typedef unsigned long long u64;

#define DDIM   64
#define BBIG   64
#define BSPLIT 2                    // CTAs along b
#define BSUB   (BBIG / BSPLIT)      // 32 b-rows per CTA
#define BLOCK  352
#define BTILE  8
#define NPASS  (BSUB / BTILE)       // 4

__device__ __forceinline__ u64 f32x2_add(u64 a, u64 b) {
    u64 r;
    asm("add.rn.f32x2 %0, %1, %2;" : "=l"(r) : "l"(a), "l"(b));
    return r;
}
__device__ __forceinline__ u64 f32x2_abs(u64 a) {
    u64 r;
    asm("and.b64 %0, %1, 0x7FFFFFFF7FFFFFFF;" : "=l"(r) : "l"(a));
    return r;
}
__device__ __forceinline__ u64 pack2(float lo, float hi) {
    u64 r;
    asm("mov.b64 %0, {%1, %2};" : "=l"(r) : "f"(lo), "f"(hi));
    return r;
}

__global__ void __launch_bounds__(BLOCK, 2) wl1_kernel(
    const float* __restrict__ q,
    const float* __restrict__ X,
    const float* __restrict__ fw,
    float* __restrict__ out,
    int N)
{
    __shared__ float w_s[DDIM];
    __shared__ float q_s[BSUB * DDIM];   // w-scaled q for this CTA's b-half, 8 KB

    const int tid = threadIdx.x;
    const int b0  = blockIdx.y * BSUB;   // this CTA's first b row

    // softplus(feature_weights), numerically stable (matches jax.nn.softplus)
    if (tid < DDIM) {
        float f = fw[tid];
        w_s[tid] = fmaxf(f, 0.0f) + log1pf(expf(-fabsf(f)));
    }
    __syncthreads();

    // stage this CTA's half of q, pre-scaled by w: q'[b][d] = w[d]*q[b][d]
    for (int i = tid; i < BSUB * DDIM; i += BLOCK) {
        q_s[i] = q[b0 * DDIM + i] * w_s[i & (DDIM - 1)];
    }
    __syncthreads();

    const int n = blockIdx.x * BLOCK + tid;
    if (n >= N) return;   // no __syncthreads below

    // load this thread's X row once, scale by w, negate, pack to f32x2 pairs
    u64 nx[DDIM / 2];
    const float4* xr = reinterpret_cast<const float4*>(X + (size_t)n * DDIM);
    #pragma unroll
    for (int j = 0; j < DDIM / 4; ++j) {
        float4 v = xr[j];
        nx[2 * j]     = pack2(-(v.x * w_s[4 * j + 0]), -(v.y * w_s[4 * j + 1]));
        nx[2 * j + 1] = pack2(-(v.z * w_s[4 * j + 2]), -(v.w * w_s[4 * j + 3]));
    }

    uint32_t qbase = (uint32_t)__cvta_generic_to_shared(q_s);

    #pragma unroll
    for (int p = 0; p < NPASS; ++p) {
        u64 acc[BTILE];
        #pragma unroll
        for (int t = 0; t < BTILE; ++t) acc[t] = 0ull;

        const uint32_t pbase = qbase + (uint32_t)(p * BTILE * DDIM * 4);

        #pragma unroll
        for (int d4 = 0; d4 < DDIM / 4; ++d4) {
            #pragma unroll
            for (int t = 0; t < BTILE; ++t) {
                uint32_t addr = pbase + (uint32_t)(t * DDIM * 4 + d4 * 16);
                u64 q01, q23;
                asm("ld.shared.v2.b64 {%0, %1}, [%2];"   // broadcast LDS.128
                    : "=l"(q01), "=l"(q23) : "r"(addr));
                u64 s0 = f32x2_add(q01, nx[2 * d4]);      // q' - x'  (nx pre-negated)
                u64 s1 = f32x2_add(q23, nx[2 * d4 + 1]);
                acc[t] = f32x2_add(acc[t], f32x2_abs(s0));
                acc[t] = f32x2_add(acc[t], f32x2_abs(s1));
            }
        }

        float* op = out + (size_t)(b0 + p * BTILE) * N + n;
        #pragma unroll
        for (int t = 0; t < BTILE; ++t) {
            float lo, hi;
            asm("mov.b64 {%0, %1}, %2;" : "=f"(lo), "=f"(hi) : "l"(acc[t]));
            op[(size_t)t * N] = lo + hi;   // reduce the two packed lanes
        }
    }
}

extern "C" void kernel_launch(void* const* d_in, const int* in_sizes, int n_in,
                              void* d_out, int out_size) {
    const float* q  = (const float*)d_in[0];
    const float* X  = (const float*)d_in[1];
    const float* fw = (const float*)d_in[2];
    float* out = (float*)d_out;
    int N = in_sizes[1] / DDIM;                      // X is [N, 64]
    dim3 grid((N + BLOCK - 1) / BLOCK, BSPLIT);      // (143, 2) @ N=50000
    wl1_kernel<<<grid, BLOCK>>>(q, X, fw, out, N);
}